// round 15
// baseline (speedup 1.0000x reference)
#include <cuda_runtime.h>
#include <cstdint>
#include <cstddef>

#define BATCH 1024
#define LSEQ  512
#define DIM   64
#define KCAP  8
#define NEGV  (-65535.0f)
#define NTHREADS 1024
#define GRID  148
#define CPS 10
#define SSS 68     // S row stride (conflict-free LDS.32 and LDS.128 patterns)
#define CSS 68     // Cs/high row stride

// ---- shared memory layout (float offsets) ----
#define WT0_OFF   0          // W^T buf0 [512][8]      4096
#define WT1_OFF   4096       // W^T buf1 [512][8]      4096
#define XS_OFF    8192       // X [512][64], 16B-chunk swizzled (chunk ^= row&15)
#define SS_OFF    40960      // S [64][68]             4352
#define CPART_OFF 45312      // pass1 partials [16][64][10]; first 4096 aliased as
                             // softmax k-major scratch SMX during step 4
#define CP_OFF    55552      // C' [8][64]             512
#define CS_OFF    56064      // Cs/high [8][68]        544
#define SCALE_OFF 56608      // squash scale [64]      64
#define HST_OFF   56672      // hs^T [64][8]           512
#define SMEM_FLOATS 57184
#define SMEM_BYTES  (SMEM_FLOATS * 4)   // 228736 B (<= 232448 opt-in)

__device__ float g_B[KCAP * LSEQ];
__device__ float g_scratch[GRID * KCAP * LSEQ];    // per-CTA accumulated deltas (2.4MB)
__device__ float g_part[16 * KCAP * LSEQ];         // stage-1 partials (256KB)

__device__ __forceinline__ void cp_async16(uint32_t sa, const void* ga) {
    asm volatile("cp.async.cg.shared.global [%0], [%1], 16;" :: "r"(sa), "l"(ga));
}
__device__ __forceinline__ void cp_commit() {
    asm volatile("cp.async.commit_group;" ::: "memory");
}
template<int N>
__device__ __forceinline__ void cp_wait() {
    asm volatile("cp.async.wait_group %0;" :: "n"(N) : "memory");
}
__device__ __forceinline__ void bar_epi() {   // named barrier 1: warps 8..23 (512 thr)
    asm volatile("bar.sync 1, 512;" ::: "memory");
}
__device__ __forceinline__ void bar_soft() {  // named barrier 2: warps 0..7 (256 thr)
    asm volatile("bar.sync 2, 256;" ::: "memory");
}
__device__ __forceinline__ unsigned long long pack2(float v) {
    unsigned long long r;
    asm("mov.b64 %0, {%1, %1};" : "=l"(r) : "r"(__float_as_uint(v)));
    return r;
}
__device__ __forceinline__ void fma2(unsigned long long& acc,
                                     unsigned long long a, unsigned long long b) {
    asm("fma.rn.f32x2 %0, %1, %2, %0;" : "+l"(acc) : "l"(a), "l"(b));
}
__device__ __forceinline__ unsigned long long add2(unsigned long long a,
                                                   unsigned long long b) {
    unsigned long long r;
    asm("add.rn.f32x2 %0, %1, %2;" : "=l"(r) : "l"(a), "l"(b));
    return r;
}

// Issue this warp's 16 X rows (2 commit groups of 8 rows), swizzled store.
__device__ __forceinline__ void issue_rows(const float* __restrict__ X, int b,
                                           uint32_t xs_base, int row0, int lane) {
    const float* Xg = X + (size_t)b * (LSEQ * DIM);
    #pragma unroll
    for (int g2 = 0; g2 < 2; g2++) {
        #pragma unroll
        for (int h = 0; h < 4; h++) {
            int s   = lane + 32 * h;               // 0..127
            int r8  = s >> 4;
            int col = s & 15;                      // 16B data chunk
            int row = row0 + 8 * g2 + r8;
            int sw  = col ^ (row & 15);            // swizzled chunk
            cp_async16(xs_base + (uint32_t)(row * 256 + sw * 16),
                       (const void*)(Xg + row * DIM + col * 4));
        }
        cp_commit();
    }
}

// Masked softmax for batch b into wtn (warps 0..7 only; k = warp id).
// Phase 1: compute + store k-major into SMX (CPART alias, conflict-free banks).
// Phase 2: cooperative transpose SMX -> wtn[l][8] with vectorized stores.
__device__ __forceinline__ void do_softmax(float* __restrict__ sm,
                                           float* __restrict__ wtn,
                                           const int* __restrict__ seqlen,
                                           int b, int k, int lane) {
    const int slen = seqlen[b];
    float v[16];
    #pragma unroll
    for (int j = 0; j < 16; j++) {
        int l = lane + 32 * j;
        float bv = g_B[k * LSEQ + l];
        v[j] = (l < slen) ? bv : NEGV;
    }
    float m = v[0];
    #pragma unroll
    for (int j = 1; j < 16; j++) m = fmaxf(m, v[j]);
    #pragma unroll
    for (int off = 16; off > 0; off >>= 1)
        m = fmaxf(m, __shfl_xor_sync(0xffffffffu, m, off));
    float s = 0.f;
    #pragma unroll
    for (int j = 0; j < 16; j++) { v[j] = __expf(v[j] - m); s += v[j]; }
    #pragma unroll
    for (int off = 16; off > 0; off >>= 1)
        s += __shfl_xor_sync(0xffffffffu, s, off);
    float inv = 1.0f / s;

    float* smx = &sm[CPART_OFF];               // k-major scratch [8][512]
    #pragma unroll
    for (int j = 0; j < 16; j++)
        smx[k * 512 + lane + 32 * j] = v[j] * inv;   // bank = lane: conflict-free
    bar_soft();

    // transpose: t8 = global softmax lane 0..255 -> rows 2*t8, 2*t8+1
    const int t8 = k * 32 + lane;
    float2 r[8];
    #pragma unroll
    for (int kk = 0; kk < 8; kk++)
        r[kk] = *(const float2*)&smx[kk * 512 + 2 * t8];
    float4 a0 = make_float4(r[0].x, r[1].x, r[2].x, r[3].x);
    float4 a1 = make_float4(r[4].x, r[5].x, r[6].x, r[7].x);
    float4 b0 = make_float4(r[0].y, r[1].y, r[2].y, r[3].y);
    float4 b1 = make_float4(r[4].y, r[5].y, r[6].y, r[7].y);
    *(float4*)&wtn[(2 * t8) * 8]         = a0;
    *(float4*)&wtn[(2 * t8) * 8 + 4]     = a1;
    *(float4*)&wtn[(2 * t8 + 1) * 8]     = b0;
    *(float4*)&wtn[(2 * t8 + 1) * 8 + 4] = b1;
}

// Persistent kernel: one routing iteration. Warp-specialized step 4:
// warps 0-7 softmax(n+1), warps 8-23 epilogue, warps 24-31 idle.
// Pass-2 deltas accumulate in registers across all batches of this CTA.
template<int LAST>
__global__ void __launch_bounds__(NTHREADS, 1)
route_kernel(const float* __restrict__ X, const float* __restrict__ Sg,
             const int* __restrict__ seqlen, float* __restrict__ out)
{
    extern __shared__ float sm[];
    const int tid  = threadIdx.x;
    const int w    = tid >> 5;            // 32 warps
    const int lane = tid & 31;
    const uint32_t xs_base = (uint32_t)__cvta_generic_to_shared(&sm[XS_OFF]);
    const int row0 = w * 16;              // this warp's X rows [row0, row0+16)

    int b = blockIdx.x;

    // prologue
    issue_rows(X, b, xs_base, row0, lane);
    {
        int j = tid;                      // 1024 float4s = S [64][64]
        int d = j >> 4, o4 = (j & 15) * 4;
        float4 v = *(const float4*)(Sg + j * 4);
        float* p = &sm[SS_OFF + d * SSS + o4];
        p[0] = v.x; p[1] = v.y; p[2] = v.z; p[3] = v.w;
    }
    if (w < 8) do_softmax(sm, &sm[WT0_OFF], seqlen, b, w, lane);
    __syncthreads();

    // cross-batch delta accumulators (pass 2), fixed (row, ks) per thread
    unsigned long long dsum[2] = {0ull, 0ull};

    int par = 0;
    for (; b < BATCH; b += GRID, par ^= 1) {
        const int bn = b + GRID;
        const float* wt  = &sm[par ? WT1_OFF : WT0_OFF];
        float*       wtn = &sm[par ? WT0_OFF : WT1_OFF];

        // ---- pass 1: C'[k][d] = sum_l W[k][l]*X[l][d]; warp-private rows ----
        unsigned long long acc2[8];
        #pragma unroll
        for (int i = 0; i < 8; i++) acc2[i] = 0ull;

        #pragma unroll
        for (int g2 = 0; g2 < 2; g2++) {
            if (g2 == 0) cp_wait<1>(); else cp_wait<0>();
            __syncwarp();
            #pragma unroll
            for (int r = 0; r < 8; r++) {
                int row = row0 + 8 * g2 + r;
                int rsw = row & 15;
                float xv0 = sm[XS_OFF + row * 64 +
                               ((((lane >> 2)    ) ^ rsw) << 2) + (lane & 3)];
                float xv1 = sm[XS_OFF + row * 64 +
                               ((((lane >> 2) + 8) ^ rsw) << 2) + (lane & 3)];
                ulonglong2 wA = *(const ulonglong2*)&wt[row * 8];
                ulonglong2 wB = *(const ulonglong2*)&wt[row * 8 + 4];
                unsigned long long xx0 = pack2(xv0);
                unsigned long long xx1 = pack2(xv1);
                fma2(acc2[0], xx0, wA.x); fma2(acc2[1], xx0, wA.y);
                fma2(acc2[2], xx0, wB.x); fma2(acc2[3], xx0, wB.y);
                fma2(acc2[4], xx1, wA.x); fma2(acc2[5], xx1, wA.y);
                fma2(acc2[6], xx1, wB.x); fma2(acc2[7], xx1, wB.y);
            }
        }

        // LAST: X dead after pass1 -> prefetch own rows now
        if (LAST && bn < BATCH) issue_rows(X, bn, xs_base, row0, lane);

        // ---- two-wave cross-warp reduction into CPART [16][64][10] ----
        if (w < 16) {
            #pragma unroll
            for (int dd = 0; dd < 2; dd++)
                #pragma unroll
                for (int kp = 0; kp < 4; kp++) {
                    int d = lane + 32 * dd;
                    *(unsigned long long*)&sm[CPART_OFF + w * 640 + d * CPS + 2 * kp]
                        = acc2[dd * 4 + kp];
                }
        }
        __syncthreads();
        if (w >= 16) {
            int p = w - 16;
            #pragma unroll
            for (int dd = 0; dd < 2; dd++)
                #pragma unroll
                for (int kp = 0; kp < 4; kp++) {
                    int d = lane + 32 * dd;
                    unsigned long long* ptr =
                        (unsigned long long*)&sm[CPART_OFF + p * 640 + d * CPS + 2 * kp];
                    *ptr = add2(*ptr, acc2[dd * 4 + kp]);
                }
        }
        __syncthreads();
        if (tid < 512) {
            int k = tid >> 6, d = tid & 63;
            float s = 0.f;
            #pragma unroll
            for (int p = 0; p < 16; p++) s += sm[CPART_OFF + p * 640 + d * CPS + k];
            sm[CP_OFF + k * 64 + d] = s;
        }
        __syncthreads();   // CPART now dead -> SMX alias usable by softmax

        // ---- step 4: softmax(n+1) on warps 0-7 || epilogue on warps 8-23 ----
        if (w < 8) {
            if (bn < BATCH) do_softmax(sm, wtn, seqlen, bn, w, lane);
        } else if (w < 24) {
            const int t = tid - 256;          // 0..511
            const int k = t >> 6, o = t & 63; // warp spans one k

            // Cs[k][o] = sum_d C'[k][d]*S[d][o]  (CP broadcast 4-vectorized)
            float a0 = 0.f, a1 = 0.f;
            #pragma unroll
            for (int d4 = 0; d4 < 64; d4 += 4) {
                float4 cp = *(const float4*)&sm[CP_OFF + k * 64 + d4];   // 1-wf bcast
                a0 += cp.x * sm[SS_OFF + (d4    ) * SSS + o];
                a1 += cp.y * sm[SS_OFF + (d4 + 1) * SSS + o];
                a0 += cp.z * sm[SS_OFF + (d4 + 2) * SSS + o];
                a1 += cp.w * sm[SS_OFF + (d4 + 3) * SSS + o];
            }
            sm[CS_OFF + k * CSS + o] = a0 + a1;
            bar_epi();

            if (t < 64) {                     // squash scale (2 warps)
                float sq = 0.f;
                #pragma unroll
                for (int k8 = 0; k8 < 8; k8++) {
                    float cv = sm[CS_OFF + k8 * CSS + t];
                    sq += cv * cv;
                }
                sm[SCALE_OFF + t] = (sq / (1.0f + sq)) * rsqrtf(sq + 1e-9f);
            }
            bar_epi();

            float hv = sm[SCALE_OFF + o] * sm[CS_OFF + k * CSS + o];
            if (LAST) {
                out[(size_t)b * 512 + t] = hv;            // t == k*64+o
            } else {
                sm[CS_OFF + k * CSS + o] = hv;            // high, in place
                bar_epi();
                // hs[k][i] = sum_o high[k][o]*S[i][o] -> hs^T[i][k]
                // re-indexed: hk = t&7 (8 rows, 1-wf bcast), hi = t>>3 (4 rows, 1-wf)
                const int hk = t & 7, hi = t >> 3;
                float h0 = 0.f, h1 = 0.f;
                #pragma unroll
                for (int oo = 0; oo < 64; oo += 4) {
                    float4 hb = *(const float4*)&sm[CS_OFF + hk * CSS + oo];
                    float4 sv = *(const float4*)&sm[SS_OFF + hi * SSS + oo];
                    h0 += hb.x * sv.x + hb.z * sv.z;
                    h1 += hb.y * sv.y + hb.w * sv.w;
                }
                sm[HST_OFF + hi * 8 + hk] = h0 + h1;
            }
        }
        __syncthreads();   // joins soft/epi/idle; publishes wtn + HST

        if (!LAST) {
            // ---- pass 2 (own rows): delta[k][l] = sum_i hs[k][i]*X[l][i] ----
            const int row = row0 + (lane >> 1);
            const int ks  = lane & 1;          // capsules [4ks, 4ks+4)
            const int rsw = row & 15;
            unsigned long long dacc2[2] = {0ull, 0ull};
            #pragma unroll
            for (int q = 0; q < 16; q++) {
                float4 x = *(const float4*)&sm[XS_OFF + row * 64 + ((q ^ rsw) << 2)];
                #pragma unroll
                for (int r = 0; r < 4; r++) {
                    float xvf = (r == 0) ? x.x : (r == 1) ? x.y : (r == 2) ? x.z : x.w;
                    unsigned long long xx = pack2(xvf);
                    ulonglong2 hA =
                        *(const ulonglong2*)&sm[HST_OFF + (q * 4 + r) * 8 + 4 * ks];
                    fma2(dacc2[0], xx, hA.x);
                    fma2(dacc2[1], xx, hA.y);
                }
            }
            dsum[0] = add2(dsum[0], dacc2[0]);
            dsum[1] = add2(dsum[1], dacc2[1]);

            // own rows dead -> prefetch next batch (no barrier to next pass1)
            if (bn < BATCH) issue_rows(X, bn, xs_base, row0, lane);
        }
    }

    if (!LAST) {
        // single store of this CTA's accumulated deltas: layout [cta][k][l]
        const int row = row0 + (lane >> 1);
        const int ks  = lane & 1;
        float* sc = &g_scratch[(size_t)blockIdx.x * 4096 + row];
        unsigned int u0, u1, u2, u3;
        asm("mov.b64 {%0, %1}, %2;" : "=r"(u0), "=r"(u1) : "l"(dsum[0]));
        asm("mov.b64 {%0, %1}, %2;" : "=r"(u2), "=r"(u3) : "l"(dsum[1]));
        sc[(4 * ks + 0) * 512] = __uint_as_float(u0);
        sc[(4 * ks + 1) * 512] = __uint_as_float(u1);
        sc[(4 * ks + 2) * 512] = __uint_as_float(u2);
        sc[(4 * ks + 3) * 512] = __uint_as_float(u3);
    }
}

// Two-stage deterministic 148-way reduction into g_B (full-chip parallel).
__global__ void reduce_stage1() {
    int j  = blockIdx.x * 256 + threadIdx.x;     // 0..4095 over [k][l]
    int yb = blockIdx.y;                          // 0..15
    float s = 0.f;
    for (int c = yb; c < GRID; c += 16) s += g_scratch[(size_t)c * 4096 + j];
    g_part[(size_t)yb * 4096 + j] = s;
}
__global__ void reduce_stage2() {
    int j = blockIdx.x * 256 + threadIdx.x;
    float s = 0.f;
    #pragma unroll
    for (int p = 0; p < 16; p++) s += g_part[(size_t)p * 4096 + j];
    g_B[j] += s;
}

extern "C" void kernel_launch(void* const* d_in, const int* in_sizes, int n_in,
                              void* d_out, int out_size)
{
    const float* X     = (const float*)d_in[0];  // low_capsule [1024,512,64]
    const float* Binit = (const float*)d_in[1];  // B_init [1,8,512]
    const float* S     = (const float*)d_in[2];  // S [64,64]
    const int*   seq   = (const int*)d_in[3];    // seq_len [1024,1]
    float* out = (float*)d_out;

    cudaFuncSetAttribute(route_kernel<0>, cudaFuncAttributeMaxDynamicSharedMemorySize, SMEM_BYTES);
    cudaFuncSetAttribute(route_kernel<1>, cudaFuncAttributeMaxDynamicSharedMemorySize, SMEM_BYTES);

    void* bptr = nullptr;
    cudaGetSymbolAddress(&bptr, g_B);
    cudaMemcpyAsync(bptr, Binit, KCAP * LSEQ * sizeof(float),
                    cudaMemcpyDeviceToDevice, 0);

    // iter 0
    route_kernel<0><<<GRID, NTHREADS, SMEM_BYTES>>>(X, S, seq, out);
    reduce_stage1<<<dim3(16, 16), 256>>>();
    reduce_stage2<<<16, 256>>>();
    // iter 1
    route_kernel<0><<<GRID, NTHREADS, SMEM_BYTES>>>(X, S, seq, out);
    reduce_stage1<<<dim3(16, 16), 256>>>();
    reduce_stage2<<<16, 256>>>();
    // iter 2 (final): writes high
    route_kernel<1><<<GRID, NTHREADS, SMEM_BYTES>>>(X, S, seq, out);
}

// round 16
// speedup vs baseline: 1.0088x; 1.0088x over previous
#include <cuda_runtime.h>
#include <cstdint>
#include <cstddef>

#define BATCH 1024
#define LSEQ  512
#define DIM   64
#define KCAP  8
#define NEGV  (-65535.0f)
#define NTHREADS 1024
#define GRID  148
#define CPS 10
#define SSS 68     // S row stride (conflict-free LDS.32 and LDS.128 patterns)
#define CSS 68     // Cs/high row stride

// ---- shared memory layout (float offsets) ----
#define WT0_OFF   0          // W^T buf0 [512][8]      4096
#define WT1_OFF   4096       // W^T buf1 [512][8]      4096
#define XS_OFF    8192       // X [512][64], 16B-chunk swizzled (chunk ^= row&15)
#define SS_OFF    40960      // S [64][68]             4352
#define CPART_OFF 45312      // pass1 partials [16][64][10]; aliased as softmax SMX
                             // and as boundary-reduce scratch (both when dead)
#define CP_OFF    55552      // C' [8][64]             512
#define CS_OFF    56064      // Cs/high [8][68]        544
#define SCALE_OFF 56608      // squash scale [64]      64
#define HST_OFF   56672      // hs^T [64][8]           512
#define SMEM_FLOATS 57184
#define SMEM_BYTES  (SMEM_FLOATS * 4)   // 228736 B (<= 232448 opt-in)

__device__ float g_B[KCAP * LSEQ];
__device__ float g_scratch[GRID * KCAP * LSEQ];    // per-CTA accumulated deltas (2.4MB)
__device__ unsigned g_cnt = 0;                     // grid barrier state
__device__ volatile unsigned g_gen = 0;

__device__ __forceinline__ void cp_async16(uint32_t sa, const void* ga) {
    asm volatile("cp.async.cg.shared.global [%0], [%1], 16;" :: "r"(sa), "l"(ga));
}
__device__ __forceinline__ void cp_commit() {
    asm volatile("cp.async.commit_group;" ::: "memory");
}
template<int N>
__device__ __forceinline__ void cp_wait() {
    asm volatile("cp.async.wait_group %0;" :: "n"(N) : "memory");
}
__device__ __forceinline__ void bar_epi() {   // named barrier 1: warps 8..23 (512 thr)
    asm volatile("bar.sync 1, 512;" ::: "memory");
}
__device__ __forceinline__ void bar_soft() {  // named barrier 2: warps 0..7 (256 thr)
    asm volatile("bar.sync 2, 256;" ::: "memory");
}
__device__ __forceinline__ unsigned long long pack2(float v) {
    unsigned long long r;
    asm("mov.b64 %0, {%1, %1};" : "=l"(r) : "r"(__float_as_uint(v)));
    return r;
}
__device__ __forceinline__ void fma2(unsigned long long& acc,
                                     unsigned long long a, unsigned long long b) {
    asm("fma.rn.f32x2 %0, %1, %2, %0;" : "+l"(acc) : "l"(a), "l"(b));
}
__device__ __forceinline__ unsigned long long add2(unsigned long long a,
                                                   unsigned long long b) {
    unsigned long long r;
    asm("add.rn.f32x2 %0, %1, %2;" : "=l"(r) : "l"(a), "l"(b));
    return r;
}

// Software grid barrier. Safe: grid=148 CTAs, 1 CTA/SM (228.7KB smem), 152 SMs
// on GB300 -> all CTAs co-resident. Deterministic; no data-dependent ordering.
__device__ __forceinline__ void grid_sync() {
    __syncthreads();
    if (threadIdx.x == 0) {
        unsigned gen = g_gen;
        __threadfence();                      // publish prior global stores
        if (atomicAdd(&g_cnt, 1u) == GRID - 1) {
            g_cnt = 0;
            __threadfence();
            g_gen = gen + 1;
        } else {
            while (g_gen == gen) { }
        }
    }
    __syncthreads();
}

// Issue this warp's 16 X rows (2 commit groups of 8 rows), swizzled store.
__device__ __forceinline__ void issue_rows(const float* __restrict__ X, int b,
                                           uint32_t xs_base, int row0, int lane) {
    const float* Xg = X + (size_t)b * (LSEQ * DIM);
    #pragma unroll
    for (int g2 = 0; g2 < 2; g2++) {
        #pragma unroll
        for (int h = 0; h < 4; h++) {
            int s   = lane + 32 * h;               // 0..127
            int r8  = s >> 4;
            int col = s & 15;                      // 16B data chunk
            int row = row0 + 8 * g2 + r8;
            int sw  = col ^ (row & 15);            // swizzled chunk
            cp_async16(xs_base + (uint32_t)(row * 256 + sw * 16),
                       (const void*)(Xg + row * DIM + col * 4));
        }
        cp_commit();
    }
}

// Masked softmax for batch b into wtn (warps 0..7 only; k = warp id).
// g_B read via __ldcg: it is updated by other CTAs within this launch.
__device__ __forceinline__ void do_softmax(float* __restrict__ sm,
                                           float* __restrict__ wtn,
                                           const int* __restrict__ seqlen,
                                           int b, int k, int lane) {
    const int slen = seqlen[b];
    float v[16];
    #pragma unroll
    for (int j = 0; j < 16; j++) {
        int l = lane + 32 * j;
        float bv = __ldcg(&g_B[k * LSEQ + l]);
        v[j] = (l < slen) ? bv : NEGV;
    }
    float m = v[0];
    #pragma unroll
    for (int j = 1; j < 16; j++) m = fmaxf(m, v[j]);
    #pragma unroll
    for (int off = 16; off > 0; off >>= 1)
        m = fmaxf(m, __shfl_xor_sync(0xffffffffu, m, off));
    float s = 0.f;
    #pragma unroll
    for (int j = 0; j < 16; j++) { v[j] = __expf(v[j] - m); s += v[j]; }
    #pragma unroll
    for (int off = 16; off > 0; off >>= 1)
        s += __shfl_xor_sync(0xffffffffu, s, off);
    float inv = 1.0f / s;

    float* smx = &sm[CPART_OFF];               // k-major scratch [8][512]
    #pragma unroll
    for (int j = 0; j < 16; j++)
        smx[k * 512 + lane + 32 * j] = v[j] * inv;   // bank = lane: conflict-free
    bar_soft();

    const int t8 = k * 32 + lane;              // 0..255 -> rows 2*t8, 2*t8+1
    float2 r[8];
    #pragma unroll
    for (int kk = 0; kk < 8; kk++)
        r[kk] = *(const float2*)&smx[kk * 512 + 2 * t8];
    float4 a0 = make_float4(r[0].x, r[1].x, r[2].x, r[3].x);
    float4 a1 = make_float4(r[4].x, r[5].x, r[6].x, r[7].x);
    float4 b0 = make_float4(r[0].y, r[1].y, r[2].y, r[3].y);
    float4 b1 = make_float4(r[4].y, r[5].y, r[6].y, r[7].y);
    *(float4*)&wtn[(2 * t8) * 8]         = a0;
    *(float4*)&wtn[(2 * t8) * 8 + 4]     = a1;
    *(float4*)&wtn[(2 * t8 + 1) * 8]     = b0;
    *(float4*)&wtn[(2 * t8 + 1) * 8 + 4] = b1;
}

// One routing iteration (batch loop). Precondition: WT0 holds softmax(b0),
// X(b0) cp.async groups in flight, S staged. Postcondition (non-LAST):
// per-CTA deltas stored to g_scratch; next-iteration b0 X prefetch in flight.
template<int LAST>
__device__ __forceinline__ void run_batches(float* sm,
                                            const float* __restrict__ X,
                                            const int* __restrict__ seqlen,
                                            float* __restrict__ out,
                                            uint32_t xs_base) {
    const int tid  = threadIdx.x;
    const int w    = tid >> 5;
    const int lane = tid & 31;
    const int row0 = w * 16;

    unsigned long long dsum[2] = {0ull, 0ull};

    int b = blockIdx.x;
    int par = 0;
    for (; b < BATCH; b += GRID, par ^= 1) {
        const int bn = b + GRID;
        const float* wt  = &sm[par ? WT1_OFF : WT0_OFF];
        float*       wtn = &sm[par ? WT0_OFF : WT1_OFF];

        // ---- pass 1: C'[k][d] = sum_l W[k][l]*X[l][d]; warp-private rows ----
        unsigned long long acc2[8];
        #pragma unroll
        for (int i = 0; i < 8; i++) acc2[i] = 0ull;

        #pragma unroll
        for (int g2 = 0; g2 < 2; g2++) {
            if (g2 == 0) cp_wait<1>(); else cp_wait<0>();
            __syncwarp();
            #pragma unroll
            for (int r = 0; r < 8; r++) {
                int row = row0 + 8 * g2 + r;
                int rsw = row & 15;
                float xv0 = sm[XS_OFF + row * 64 +
                               ((((lane >> 2)    ) ^ rsw) << 2) + (lane & 3)];
                float xv1 = sm[XS_OFF + row * 64 +
                               ((((lane >> 2) + 8) ^ rsw) << 2) + (lane & 3)];
                ulonglong2 wA = *(const ulonglong2*)&wt[row * 8];
                ulonglong2 wB = *(const ulonglong2*)&wt[row * 8 + 4];
                unsigned long long xx0 = pack2(xv0);
                unsigned long long xx1 = pack2(xv1);
                fma2(acc2[0], xx0, wA.x); fma2(acc2[1], xx0, wA.y);
                fma2(acc2[2], xx0, wB.x); fma2(acc2[3], xx0, wB.y);
                fma2(acc2[4], xx1, wA.x); fma2(acc2[5], xx1, wA.y);
                fma2(acc2[6], xx1, wB.x); fma2(acc2[7], xx1, wB.y);
            }
        }

        // LAST: X dead after pass1 -> prefetch own rows now
        if (LAST && bn < BATCH) issue_rows(X, bn, xs_base, row0, lane);

        // ---- two-wave cross-warp reduction into CPART [16][64][10] ----
        if (w < 16) {
            #pragma unroll
            for (int dd = 0; dd < 2; dd++)
                #pragma unroll
                for (int kp = 0; kp < 4; kp++) {
                    int d = lane + 32 * dd;
                    *(unsigned long long*)&sm[CPART_OFF + w * 640 + d * CPS + 2 * kp]
                        = acc2[dd * 4 + kp];
                }
        }
        __syncthreads();
        if (w >= 16) {
            int p = w - 16;
            #pragma unroll
            for (int dd = 0; dd < 2; dd++)
                #pragma unroll
                for (int kp = 0; kp < 4; kp++) {
                    int d = lane + 32 * dd;
                    unsigned long long* ptr =
                        (unsigned long long*)&sm[CPART_OFF + p * 640 + d * CPS + 2 * kp];
                    *ptr = add2(*ptr, acc2[dd * 4 + kp]);
                }
        }
        __syncthreads();
        if (tid < 512) {
            int k = tid >> 6, d = tid & 63;
            float s = 0.f;
            #pragma unroll
            for (int p = 0; p < 16; p++) s += sm[CPART_OFF + p * 640 + d * CPS + k];
            sm[CP_OFF + k * 64 + d] = s;
        }
        __syncthreads();   // CPART now dead -> SMX alias usable by softmax

        // ---- step 4: softmax(n+1) on warps 0-7 || epilogue on warps 8-23 ----
        if (w < 8) {
            if (bn < BATCH) do_softmax(sm, wtn, seqlen, bn, w, lane);
        } else if (w < 24) {
            const int t = tid - 256;          // 0..511
            const int k = t >> 6, o = t & 63; // warp spans one k

            float a0 = 0.f, a1 = 0.f;
            #pragma unroll
            for (int d4 = 0; d4 < 64; d4 += 4) {
                float4 cp = *(const float4*)&sm[CP_OFF + k * 64 + d4];   // 1-wf bcast
                a0 += cp.x * sm[SS_OFF + (d4    ) * SSS + o];
                a1 += cp.y * sm[SS_OFF + (d4 + 1) * SSS + o];
                a0 += cp.z * sm[SS_OFF + (d4 + 2) * SSS + o];
                a1 += cp.w * sm[SS_OFF + (d4 + 3) * SSS + o];
            }
            sm[CS_OFF + k * CSS + o] = a0 + a1;
            bar_epi();

            if (t < 64) {                     // squash scale (2 warps)
                float sq = 0.f;
                #pragma unroll
                for (int k8 = 0; k8 < 8; k8++) {
                    float cv = sm[CS_OFF + k8 * CSS + t];
                    sq += cv * cv;
                }
                sm[SCALE_OFF + t] = (sq / (1.0f + sq)) * rsqrtf(sq + 1e-9f);
            }
            bar_epi();

            float hv = sm[SCALE_OFF + o] * sm[CS_OFF + k * CSS + o];
            if (LAST) {
                out[(size_t)b * 512 + t] = hv;            // t == k*64+o
            } else {
                sm[CS_OFF + k * CSS + o] = hv;            // high, in place
                bar_epi();
                const int hk = t & 7, hi = t >> 3;
                float h0 = 0.f, h1 = 0.f;
                #pragma unroll
                for (int oo = 0; oo < 64; oo += 4) {
                    float4 hb = *(const float4*)&sm[CS_OFF + hk * CSS + oo];
                    float4 sv = *(const float4*)&sm[SS_OFF + hi * SSS + oo];
                    h0 += hb.x * sv.x + hb.z * sv.z;
                    h1 += hb.y * sv.y + hb.w * sv.w;
                }
                sm[HST_OFF + hi * 8 + hk] = h0 + h1;
            }
        }
        __syncthreads();   // joins soft/epi/idle; publishes wtn + HST

        if (!LAST) {
            // ---- pass 2 (own rows): delta[k][l] = sum_i hs[k][i]*X[l][i] ----
            const int row = row0 + (lane >> 1);
            const int ks  = lane & 1;          // capsules [4ks, 4ks+4)
            const int rsw = row & 15;
            unsigned long long dacc2[2] = {0ull, 0ull};
            #pragma unroll
            for (int q = 0; q < 16; q++) {
                float4 x = *(const float4*)&sm[XS_OFF + row * 64 + ((q ^ rsw) << 2)];
                #pragma unroll
                for (int r = 0; r < 4; r++) {
                    float xvf = (r == 0) ? x.x : (r == 1) ? x.y : (r == 2) ? x.z : x.w;
                    unsigned long long xx = pack2(xvf);
                    ulonglong2 hA =
                        *(const ulonglong2*)&sm[HST_OFF + (q * 4 + r) * 8 + 4 * ks];
                    fma2(dacc2[0], xx, hA.x);
                    fma2(dacc2[1], xx, hA.y);
                }
            }
            dsum[0] = add2(dsum[0], dacc2[0]);
            dsum[1] = add2(dsum[1], dacc2[1]);

            if (bn < BATCH) issue_rows(X, bn, xs_base, row0, lane);
        }
    }

    if (!LAST) {
        // prefetch NEXT ITERATION's first batch (own rows dead) so the load
        // overlaps the cross-CTA reduction + grid syncs
        issue_rows(X, blockIdx.x, xs_base, row0, lane);

        // store this CTA's accumulated deltas: layout [cta][k][l]
        const int row = row0 + (lane >> 1);
        const int ks  = lane & 1;
        float* sc = &g_scratch[(size_t)blockIdx.x * 4096 + row];
        unsigned int u0, u1, u2, u3;
        asm("mov.b64 {%0, %1}, %2;" : "=r"(u0), "=r"(u1) : "l"(dsum[0]));
        asm("mov.b64 {%0, %1}, %2;" : "=r"(u2), "=r"(u3) : "l"(dsum[1]));
        sc[(4 * ks + 0) * 512] = __uint_as_float(u0);
        sc[(4 * ks + 1) * 512] = __uint_as_float(u1);
        sc[(4 * ks + 2) * 512] = __uint_as_float(u2);
        sc[(4 * ks + 3) * 512] = __uint_as_float(u3);
    }
}

// Cross-iteration boundary: publish deltas, 148-way deterministic reduce into
// g_B (CTAs 0-15, fixed order), publish g_B. CPART smem reused as scratch.
__device__ __forceinline__ void boundary_reduce(float* sm) {
    const int tid = threadIdx.x;
    grid_sync();                               // deltas visible (via fences)
    if (blockIdx.x < 16) {
        int j = blockIdx.x * 256 + (tid & 255);
        int q = tid >> 8;                      // quarter: 37 CTAs each (4*37=148)
        float s = 0.f;
        #pragma unroll 4
        for (int c = q * 37; c < q * 37 + 37; c++)
            s += __ldcg(&g_scratch[(size_t)c * 4096 + j]);
        sm[CPART_OFF + q * 256 + (tid & 255)] = s;
        __syncthreads();
        if (tid < 256) {
            float tot = sm[CPART_OFF + tid]       + sm[CPART_OFF + 256 + tid]
                      + sm[CPART_OFF + 512 + tid] + sm[CPART_OFF + 768 + tid];
            int jj = blockIdx.x * 256 + tid;
            g_B[jj] += tot;                    // own slice: SM-local coherent
        }
    }
    grid_sync();                               // g_B visible to all (__ldcg reads)
}

// Fused persistent kernel: 3 routing iterations + 2 in-kernel reductions.
__global__ void __launch_bounds__(NTHREADS, 1)
route_fused(const float* __restrict__ X, const float* __restrict__ Sg,
            const int* __restrict__ seqlen, float* __restrict__ out)
{
    extern __shared__ float sm[];
    const int tid  = threadIdx.x;
    const int w    = tid >> 5;
    const int lane = tid & 31;
    const uint32_t xs_base = (uint32_t)__cvta_generic_to_shared(&sm[XS_OFF]);
    const int row0 = w * 16;

    // prologue: X(b0) + S staging + softmax(b0)
    issue_rows(X, blockIdx.x, xs_base, row0, lane);
    {
        int j = tid;                      // 1024 float4s = S [64][64]
        int d = j >> 4, o4 = (j & 15) * 4;
        float4 v = *(const float4*)(Sg + j * 4);
        float* p = &sm[SS_OFF + d * SSS + o4];
        p[0] = v.x; p[1] = v.y; p[2] = v.z; p[3] = v.w;
    }
    if (w < 8) do_softmax(sm, &sm[WT0_OFF], seqlen, blockIdx.x, w, lane);
    __syncthreads();

    // iteration 0
    run_batches<0>(sm, X, seqlen, out, xs_base);
    boundary_reduce(sm);
    if (w < 8) do_softmax(sm, &sm[WT0_OFF], seqlen, blockIdx.x, w, lane);
    __syncthreads();

    // iteration 1
    run_batches<0>(sm, X, seqlen, out, xs_base);
    boundary_reduce(sm);
    if (w < 8) do_softmax(sm, &sm[WT0_OFF], seqlen, blockIdx.x, w, lane);
    __syncthreads();

    // iteration 2 (final): writes high
    run_batches<1>(sm, X, seqlen, out, xs_base);
}

extern "C" void kernel_launch(void* const* d_in, const int* in_sizes, int n_in,
                              void* d_out, int out_size)
{
    const float* X     = (const float*)d_in[0];  // low_capsule [1024,512,64]
    const float* Binit = (const float*)d_in[1];  // B_init [1,8,512]
    const float* S     = (const float*)d_in[2];  // S [64,64]
    const int*   seq   = (const int*)d_in[3];    // seq_len [1024,1]
    float* out = (float*)d_out;

    cudaFuncSetAttribute(route_fused, cudaFuncAttributeMaxDynamicSharedMemorySize,
                         SMEM_BYTES);

    void* bptr = nullptr;
    cudaGetSymbolAddress(&bptr, g_B);
    cudaMemcpyAsync(bptr, Binit, KCAP * LSEQ * sizeof(float),
                    cudaMemcpyDeviceToDevice, 0);

    route_fused<<<GRID, NTHREADS, SMEM_BYTES>>>(X, S, seq, out);
}